// round 6
// baseline (speedup 1.0000x reference)
#include <cuda_runtime.h>
#include <math.h>

// Problem dims (fixed)
#define TT 512
#define BB 32
#define II 1024
#define HH 1024
#define GG 4096            // 4*H
#define KK 1024

#define PM (TT*BB)         // 16384 rows for projection GEMM
#define PN GG              // 4096
#define PK 1024

#define NB 128             // persistent grid blocks
#define NT 256             // threads per block
#define NKS 8              // K-splits in recurrent GEMM

// ---------------- scratch (device globals; no allocation allowed) ----------------
__device__ float g_xg[TT*BB*GG];        // input projection for current layer
__device__ float g_out0[TT*BB*HH];      // layer-0 hidden outputs
__device__ float g_h[2*BB*HH];          // running h per layer
__device__ float g_c[2*BB*HH];          // running c per layer
__device__ float g_part[NKS][BB*GG];    // K-split partials (deterministic reduce)

// grid barrier state
__device__ unsigned g_count = 0;
__device__ volatile unsigned g_sense_v = 0;

__device__ __forceinline__ float sigm(float x) { return 1.0f / (1.0f + expf(-x)); }

// ---- packed f32x2 helpers (FFMA2: 2x fp32 FMA throughput, only via PTX) ----
__device__ __forceinline__ unsigned long long pk2(float lo, float hi) {
    unsigned long long r;
    asm("mov.b64 %0, {%1,%2};" : "=l"(r) : "f"(lo), "f"(hi));
    return r;
}
__device__ __forceinline__ void fma2(unsigned long long& d,
                                     unsigned long long a,
                                     unsigned long long b) {
    asm("fma.rn.f32x2 %0, %1, %2, %0;" : "+l"(d) : "l"(a), "l"(b));
}
__device__ __forceinline__ float2 upk2(unsigned long long v) {
    float2 r;
    asm("mov.b64 {%0,%1}, %2;" : "=f"(r.x), "=f"(r.y) : "l"(v));
    return r;
}

__device__ __forceinline__ float ldcg(const float* p) {
    float v;
    asm volatile("ld.global.cg.f32 %0, [%1];" : "=f"(v) : "l"(p));
    return v;
}
__device__ __forceinline__ float4 ldcg4(const float* p) {
    float4 v;
    asm volatile("ld.global.cg.v4.f32 {%0,%1,%2,%3}, [%4];"
                 : "=f"(v.x), "=f"(v.y), "=f"(v.z), "=f"(v.w) : "l"(p));
    return v;
}

// sense-reversing grid barrier (all NB blocks co-resident; 128 <= 148 SMs)
__device__ __forceinline__ void gbar(unsigned* sense) {
    __syncthreads();
    if (threadIdx.x == 0) {
        unsigned s = 1u - *sense;
        *sense = s;
        __threadfence();
        if (atomicAdd(&g_count, 1u) == NB - 1u) {
            g_count = 0;
            __threadfence();
            g_sense_v = s;
        } else {
            while (g_sense_v != s) { __nanosleep(32); }
        }
    }
    __syncthreads();
}

// ---------------- init: copy h0/c0 into running state ----------------
__global__ void init_state(const float* __restrict__ h0, const float* __restrict__ c0) {
    int i = blockIdx.x * 256 + threadIdx.x;
    if (i < 2*BB*HH) {
        g_h[i] = h0[i];
        g_c[i] = c0[i];
    }
}

// ---------------- projection GEMM: C[m][n] = sum_k A[m][k]*W[n][k] + bias[n] ----
// 128x128 tile, BK=8, 8(m)x8(n) per thread, f32x2-packed along n.
__global__ __launch_bounds__(256) void proj_gemm(const float* __restrict__ A,
                                                 const float* __restrict__ W,
                                                 const float* __restrict__ bias,
                                                 float* __restrict__ C) {
    __shared__ __align__(16) float As[8][128];
    __shared__ __align__(16) float Bs[8][128];

    const int tid  = threadIdx.x;
    const int m0   = blockIdx.y * 128;
    const int n0   = blockIdx.x * 128;
    const int lRow = tid >> 1;
    const int lCol = (tid & 1) * 4;
    const int tRow = (tid >> 4) * 8;
    const int tCol = (tid & 15) * 8;

    const float* Aptr = A + (size_t)(m0 + lRow) * PK + lCol;
    const float* Wptr = W + (size_t)(n0 + lRow) * PK + lCol;

    unsigned long long acc2[8][4];   // [m][n-pair]
    #pragma unroll
    for (int i = 0; i < 8; i++)
        #pragma unroll
        for (int j = 0; j < 4; j++) acc2[i][j] = 0ull;

    float4 a = *(const float4*)(Aptr);
    float4 b = *(const float4*)(Wptr);

    for (int k0 = 0; k0 < PK; k0 += 8) {
        __syncthreads();
        As[lCol+0][lRow] = a.x; As[lCol+1][lRow] = a.y;
        As[lCol+2][lRow] = a.z; As[lCol+3][lRow] = a.w;
        Bs[lCol+0][lRow] = b.x; Bs[lCol+1][lRow] = b.y;
        Bs[lCol+2][lRow] = b.z; Bs[lCol+3][lRow] = b.w;
        __syncthreads();
        if (k0 + 8 < PK) {
            a = *(const float4*)(Aptr + k0 + 8);
            b = *(const float4*)(Wptr + k0 + 8);
        }
        #pragma unroll
        for (int k = 0; k < 8; k++) {
            float4 m1 = *(const float4*)&As[k][tRow];
            float4 m2 = *(const float4*)&As[k][tRow + 4];
            ulonglong2 n1 = *(const ulonglong2*)&Bs[k][tCol];
            ulonglong2 n2 = *(const ulonglong2*)&Bs[k][tCol + 4];
            unsigned long long rn[4] = {n1.x, n1.y, n2.x, n2.y};
            float rm[8] = {m1.x, m1.y, m1.z, m1.w, m2.x, m2.y, m2.z, m2.w};
            #pragma unroll
            for (int i = 0; i < 8; i++) {
                unsigned long long pm = pk2(rm[i], rm[i]);
                #pragma unroll
                for (int j = 0; j < 4; j++)
                    fma2(acc2[i][j], pm, rn[j]);
            }
        }
    }

    #pragma unroll
    for (int i = 0; i < 8; i++) {
        float* Crow = C + (size_t)(m0 + tRow + i) * PN + n0 + tCol;
        #pragma unroll
        for (int j = 0; j < 4; j++) {
            float2 v = upk2(acc2[i][j]);
            Crow[2*j + 0] = v.x + bias[n0 + tCol + 2*j + 0];
            Crow[2*j + 1] = v.y + bias[n0 + tCol + 2*j + 1];
        }
    }
}

// ---------------- persistent recurrence: 512 steps, one layer ----------------
// Phase A (per block): partial GEMM, gates [gt*256,+256) x k [ks*128,+128).
//   Thread tile 4(b) x 8(g), f32x2-packed along g. R L1-resident per SM.
// Phase B: 1 element (b,j) per thread; c lives in a register all 512 steps.
__global__ __launch_bounds__(NT) void recurrent_persistent(
    int layer, const float* __restrict__ R, const float* __restrict__ bh,
    const float* __restrict__ xg, float* __restrict__ out)
{
    __shared__ __align__(16) float sh[16][32];    // [k][b]
    __shared__ __align__(16) float sr[16][256];   // [k][g]

    const int tid = threadIdx.x;
    const int bid = blockIdx.x;
    const int gt  = bid >> 3;          // 0..15
    const int ks  = bid & 7;           // 0..7
    const int g0  = gt * 256;
    const int k0  = ks * 128;

    const int tb = (tid >> 5) * 4;     // batch base 0..28
    const int tg = (tid & 31) * 8;     // gate base in tile 0..248

    const int hB = tid & 31;           // batch (tid<128 only)
    const int hK = (tid >> 5) * 4;     // 0,4,8,12 (tid<128)

    float* hbuf = g_h + layer * (BB * HH);
    float* cbuf = g_c + layer * (BB * HH);
    float* mypart = g_part[ks];

    const int pidx = bid * NT + tid;   // 0..32767 — one (b,j) per thread
    const int pb = pidx >> 10;
    const int pj = pidx & (HH - 1);
    float c_reg = cbuf[pidx];

    // hoist loop-invariant phase-B operands
    float bhv[4];
    #pragma unroll
    for (int q = 0; q < 4; q++) bhv[q] = bh[q * HH + pj];
    const float* xg_base = xg + (size_t)pb * GG + pj;

    unsigned sense = g_sense_v;        // read before any block can flip it

    const float* Rrow = R + (size_t)(g0 + tid) * KK + k0;
    const float* hrow = hbuf + hB * KK + k0;

    for (int t = 0; t < TT; ++t) {
        // ---------------- phase A: partial GEMM ----------------
        unsigned long long acc2[4][4];     // [b][g-pair]
        #pragma unroll
        for (int i = 0; i < 4; i++)
            #pragma unroll
            for (int j = 0; j < 4; j++) acc2[i][j] = 0ull;

        float4 hv = make_float4(0,0,0,0);
        float4 rv[4];
        if (tid < 128) hv = ldcg4(hrow + hK);
        #pragma unroll
        for (int q = 0; q < 4; q++) rv[q] = *(const float4*)(Rrow + q * 4);

        for (int kk = 0; kk < 128; kk += 16) {
            __syncthreads();
            if (tid < 128) {
                sh[hK+0][hB] = hv.x; sh[hK+1][hB] = hv.y;
                sh[hK+2][hB] = hv.z; sh[hK+3][hB] = hv.w;
            }
            #pragma unroll
            for (int q = 0; q < 4; q++) {
                sr[q*4+0][tid] = rv[q].x; sr[q*4+1][tid] = rv[q].y;
                sr[q*4+2][tid] = rv[q].z; sr[q*4+3][tid] = rv[q].w;
            }
            __syncthreads();
            if (kk + 16 < 128) {
                if (tid < 128) hv = ldcg4(hrow + kk + 16 + hK);
                #pragma unroll
                for (int q = 0; q < 4; q++)
                    rv[q] = *(const float4*)(Rrow + kk + 16 + q * 4);
            }
            #pragma unroll
            for (int k = 0; k < 16; k++) {
                float4 hb = *(const float4*)&sh[k][tb];               // warp broadcast
                ulonglong2 r1 = *(const ulonglong2*)&sr[k][tg];       // g pairs 0,1
                ulonglong2 r2 = *(const ulonglong2*)&sr[k][tg + 4];   // g pairs 2,3
                unsigned long long rg[4] = {r1.x, r1.y, r2.x, r2.y};
                float hbf[4] = {hb.x, hb.y, hb.z, hb.w};
                #pragma unroll
                for (int i = 0; i < 4; i++) {
                    unsigned long long ph = pk2(hbf[i], hbf[i]);
                    #pragma unroll
                    for (int j = 0; j < 4; j++)
                        fma2(acc2[i][j], ph, rg[j]);
                }
            }
        }

        #pragma unroll
        for (int i = 0; i < 4; i++) {
            float2 v0 = upk2(acc2[i][0]);
            float2 v1 = upk2(acc2[i][1]);
            float2 v2 = upk2(acc2[i][2]);
            float2 v3 = upk2(acc2[i][3]);
            float* p = mypart + (size_t)(tb + i) * GG + g0 + tg;
            *(float4*)(p)     = make_float4(v0.x, v0.y, v1.x, v1.y);
            *(float4*)(p + 4) = make_float4(v2.x, v2.y, v3.x, v3.y);
        }

        gbar(&sense);   // partials published

        // ---------------- phase B: pointwise ----------------
        const float* xg_t = xg_base + (size_t)t * BB * GG;
        float pre[4];
        #pragma unroll
        for (int q = 0; q < 4; q++) {
            float v = xg_t[q * HH] + bhv[q];
            #pragma unroll
            for (int s = 0; s < NKS; s++)
                v += ldcg(&g_part[s][pb * GG + q * HH + pj]);
            pre[q] = sigm(v);
        }
        c_reg = c_reg * pre[3] + pre[2] - pre[0];
        float hnew = sigm(c_reg) - pre[1];
        hbuf[pidx] = hnew;
        out[(size_t)t * BB * HH + pidx] = hnew;

        gbar(&sense);   // h published; g_part safe to overwrite
    }

    cbuf[pidx] = c_reg;   // final cell state
}

// ---------------- finalize: write stacked (hT, cT) after main output ----------------
__global__ void finalize(float* __restrict__ out) {
    int i = blockIdx.x * 256 + threadIdx.x;
    if (i < 2 * BB * HH) {
        out[(size_t)TT * BB * HH + i] = g_h[i];
        out[(size_t)TT * BB * HH + 2 * BB * HH + i] = g_c[i];
    }
}

// ---------------- launch: 6 graph nodes total ----------------
extern "C" void kernel_launch(void* const* d_in, const int* in_sizes, int n_in,
                              void* d_out, int out_size) {
    const float* x   = (const float*)d_in[0];
    const float* h0  = (const float*)d_in[1];
    const float* c0  = (const float*)d_in[2];
    const float* W0  = (const float*)d_in[3];
    const float* R0  = (const float*)d_in[4];
    const float* bi0 = (const float*)d_in[5];
    const float* bh0 = (const float*)d_in[6];
    const float* W1  = (const float*)d_in[7];
    const float* R1  = (const float*)d_in[8];
    const float* bi1 = (const float*)d_in[9];
    const float* bh1 = (const float*)d_in[10];
    float* out = (float*)d_out;

    float *p_xg = nullptr, *p_out0 = nullptr;
    cudaGetSymbolAddress((void**)&p_xg, g_xg);
    cudaGetSymbolAddress((void**)&p_out0, g_out0);

    dim3 projGrid(PN / 128, PM / 128);     // (32, 128)

    init_state<<<256, 256>>>(h0, c0);

    proj_gemm<<<projGrid, 256>>>(x, W0, bi0, p_xg);
    recurrent_persistent<<<NB, NT>>>(0, R0, bh0, p_xg, p_out0);

    proj_gemm<<<projGrid, 256>>>(p_out0, W1, bi1, p_xg);
    recurrent_persistent<<<NB, NT>>>(1, R1, bh1, p_xg, out);

    finalize<<<256, 256>>>(out);
}

// round 7
// speedup vs baseline: 1.6530x; 1.6530x over previous
#include <cuda_runtime.h>
#include <math.h>

// Problem dims (fixed)
#define TT 512
#define BB 32
#define II 1024
#define HH 1024
#define GG 4096            // 4*H
#define KK 1024

#define PM (TT*BB)
#define PN GG
#define PK 1024

#define NB 128             // persistent grid blocks (all co-resident, <=148 SMs)
#define NT 256             // threads per block
#define NKS 8              // K-splits in recurrent GEMM

// recurrent smem layout (dynamic): R tile + h tile
#define SH_PITCH 40                        // h tile pitch (16B-aligned rows, low conflict)
#define SR_FLOATS (128*256)                // 128 k x 256 g = 128 KB
#define SH_FLOATS (128*SH_PITCH)           // 20 KB
#define DYN_SMEM_BYTES ((SR_FLOATS + SH_FLOATS) * 4)

// ---------------- scratch (device globals; no allocation allowed) ----------------
__device__ float g_xg[TT*BB*GG];
__device__ float g_out0[TT*BB*HH];
__device__ float g_h[2*BB*HH];
__device__ float g_c[2*BB*HH];
__device__ float g_part[NKS][BB*GG];

// grid barrier state
__device__ unsigned g_count = 0;
__device__ volatile unsigned g_sense_v = 0;

__device__ __forceinline__ float sigm(float x) { return 1.0f / (1.0f + expf(-x)); }

// ---- packed f32x2 helpers (FFMA2 via PTX only) ----
__device__ __forceinline__ unsigned long long pk2(float lo, float hi) {
    unsigned long long r;
    asm("mov.b64 %0, {%1,%2};" : "=l"(r) : "f"(lo), "f"(hi));
    return r;
}
__device__ __forceinline__ void fma2(unsigned long long& d,
                                     unsigned long long a,
                                     unsigned long long b) {
    asm("fma.rn.f32x2 %0, %1, %2, %0;" : "+l"(d) : "l"(a), "l"(b));
}
__device__ __forceinline__ float2 upk2(unsigned long long v) {
    float2 r;
    asm("mov.b64 {%0,%1}, %2;" : "=f"(r.x), "=f"(r.y) : "l"(v));
    return r;
}

__device__ __forceinline__ float ldcg(const float* p) {
    float v;
    asm volatile("ld.global.cg.f32 %0, [%1];" : "=f"(v) : "l"(p));
    return v;
}

// sense-reversing grid barrier, bare spin (structure validated in R6 PASS)
__device__ __forceinline__ void gbar(unsigned* sense) {
    __syncthreads();
    if (threadIdx.x == 0) {
        unsigned s = 1u - *sense;
        *sense = s;
        __threadfence();
        if (atomicAdd(&g_count, 1u) == NB - 1u) {
            g_count = 0;
            __threadfence();
            g_sense_v = s;
        } else {
            while (g_sense_v != s) { }
        }
    }
    __syncthreads();
}

// ---------------- init ----------------
__global__ void init_state(const float* __restrict__ h0, const float* __restrict__ c0) {
    int i = blockIdx.x * 256 + threadIdx.x;
    if (i < 2*BB*HH) { g_h[i] = h0[i]; g_c[i] = c0[i]; }
}

// ---------------- projection GEMM: C = A @ W^T + bias ----------------
// 128x128 tile, BK=8, 8x8 per thread with SPLIT-QUAD mapping (conflict-free LDS):
//   m rows: {4*mr..+3} u {64+4*mr..+3},  n cols: {4*nc..+3} u {64+4*nc..+3}
__global__ __launch_bounds__(256) void proj_gemm(const float* __restrict__ A,
                                                 const float* __restrict__ W,
                                                 const float* __restrict__ bias,
                                                 float* __restrict__ C) {
    __shared__ __align__(16) float As[8][128];
    __shared__ __align__(16) float Bs[8][128];

    const int tid  = threadIdx.x;
    const int m0   = blockIdx.y * 128;
    const int n0   = blockIdx.x * 128;
    const int lRow = tid >> 1;
    const int lCol = (tid & 1) * 4;
    const int mr   = tid >> 4;        // 0..15
    const int nc   = tid & 15;        // 0..15

    const float* Aptr = A + (size_t)(m0 + lRow) * PK + lCol;
    const float* Wptr = W + (size_t)(n0 + lRow) * PK + lCol;

    unsigned long long acc2[8][4];    // [m-idx][n-pair]: m 0..3 = quad1, 4..7 = quad2
    #pragma unroll
    for (int i = 0; i < 8; i++)
        #pragma unroll
        for (int j = 0; j < 4; j++) acc2[i][j] = 0ull;

    float4 a = *(const float4*)(Aptr);
    float4 b = *(const float4*)(Wptr);

    for (int k0 = 0; k0 < PK; k0 += 8) {
        __syncthreads();
        As[lCol+0][lRow] = a.x; As[lCol+1][lRow] = a.y;
        As[lCol+2][lRow] = a.z; As[lCol+3][lRow] = a.w;
        Bs[lCol+0][lRow] = b.x; Bs[lCol+1][lRow] = b.y;
        Bs[lCol+2][lRow] = b.z; Bs[lCol+3][lRow] = b.w;
        __syncthreads();
        if (k0 + 8 < PK) {
            a = *(const float4*)(Aptr + k0 + 8);
            b = *(const float4*)(Wptr + k0 + 8);
        }
        #pragma unroll
        for (int k = 0; k < 8; k++) {
            float4 m1 = *(const float4*)&As[k][4*mr];        // contiguous -> no conflict
            float4 m2 = *(const float4*)&As[k][64 + 4*mr];
            ulonglong2 n1 = *(const ulonglong2*)&Bs[k][4*nc];       // n pairs 0,1
            ulonglong2 n2 = *(const ulonglong2*)&Bs[k][64 + 4*nc];  // n pairs 2,3
            unsigned long long rn[4] = {n1.x, n1.y, n2.x, n2.y};
            float rm[8] = {m1.x, m1.y, m1.z, m1.w, m2.x, m2.y, m2.z, m2.w};
            #pragma unroll
            for (int i = 0; i < 8; i++) {
                unsigned long long pm = pk2(rm[i], rm[i]);
                #pragma unroll
                for (int j = 0; j < 4; j++)
                    fma2(acc2[i][j], pm, rn[j]);
            }
        }
    }

    #pragma unroll
    for (int i = 0; i < 8; i++) {
        int mrow = m0 + ((i < 4) ? (4*mr + i) : (64 + 4*mr + i - 4));
        float* Crow = C + (size_t)mrow * PN + n0;
        float2 v0 = upk2(acc2[i][0]);
        float2 v1 = upk2(acc2[i][1]);
        float2 v2 = upk2(acc2[i][2]);
        float2 v3 = upk2(acc2[i][3]);
        int nq1 = 4*nc, nq2 = 64 + 4*nc;
        Crow[nq1+0] = v0.x + bias[n0+nq1+0];
        Crow[nq1+1] = v0.y + bias[n0+nq1+1];
        Crow[nq1+2] = v1.x + bias[n0+nq1+2];
        Crow[nq1+3] = v1.y + bias[n0+nq1+3];
        Crow[nq2+0] = v2.x + bias[n0+nq2+0];
        Crow[nq2+1] = v2.y + bias[n0+nq2+1];
        Crow[nq2+2] = v3.x + bias[n0+nq2+2];
        Crow[nq2+3] = v3.y + bias[n0+nq2+3];
    }
}

// ---------------- persistent recurrence: 512 steps, one layer ----------------
// R slice [256 g x 128 k] parked in smem ONCE (transposed [k][g]).
// Per step: stage h [128 k x 32 b] -> smem (1 sync), sync-free compute,
// write partials, gbar, pointwise (c in register), gbar.
__global__ __launch_bounds__(NT) void recurrent_persistent(
    int layer, const float* __restrict__ R, const float* __restrict__ bh,
    const float* __restrict__ xg, float* __restrict__ out)
{
    extern __shared__ __align__(16) float dynsmem[];
    float* sr = dynsmem;               // [k][g] : 128 x 256
    float* sh = dynsmem + SR_FLOATS;   // [k][b] : 128 x SH_PITCH (b<32)

    const int tid = threadIdx.x;
    const int bid = blockIdx.x;
    const int gt  = bid >> 3;          // 0..15
    const int ks  = bid & 7;           // 0..7
    const int g0  = gt * 256;
    const int k0  = ks * 128;

    const int lq = tid & 31;           // gate quad lane: gates {4lq..} u {128+4lq..}
    const int tb = (tid >> 5) * 4;     // batch base (warp-uniform -> broadcast reads)

    float* hbuf = g_h + layer * (BB * HH);
    float* cbuf = g_c + layer * (BB * HH);
    float* mypart = g_part[ks];

    // ---- park R slice in smem, transposed (one-time) ----
    for (int it = 0; it < 128; it++) {
        int idx = it * 256 + tid;          // 0..32767
        int g = idx >> 7, k = idx & 127;   // coalesced LDG along k
        sr[k * 256 + g] = ldcg(R + (size_t)(g0 + g) * KK + k0 + k);
    }

    // pointwise identity: one element per thread
    const int pidx = bid * NT + tid;
    const int pb = pidx >> 10;
    const int pj = pidx & (HH - 1);
    float c_reg = cbuf[pidx];

    float bhv[4];
    #pragma unroll
    for (int q = 0; q < 4; q++) bhv[q] = bh[q * HH + pj];
    const float* xg_base = xg + (size_t)pb * GG + pj;

    unsigned sense = g_sense_v;

    for (int t = 0; t < TT; ++t) {
        // ---- stage h tile (transposed) ----
        #pragma unroll
        for (int it = 0; it < 16; it++) {
            int idx = it * 256 + tid;          // 0..4095
            int b = idx >> 7, k = idx & 127;   // coalesced LDG along k
            sh[k * SH_PITCH + b] = ldcg(hbuf + (size_t)b * KK + k0 + k);
        }
        __syncthreads();

        // ---- sync-free compute over 128 k ----
        unsigned long long acc2[4][4];   // [b][g-pair]: pairs 0,1 = quad1, 2,3 = quad2
        #pragma unroll
        for (int i = 0; i < 4; i++)
            #pragma unroll
            for (int j = 0; j < 4; j++) acc2[i][j] = 0ull;

        #pragma unroll 4
        for (int k = 0; k < 128; k++) {
            const float* shk = sh + k * SH_PITCH;
            const float* srk = sr + k * 256;
            float4 hb = *(const float4*)(shk + tb);                  // broadcast
            ulonglong2 r1 = *(const ulonglong2*)(srk + 4*lq);        // contiguous
            ulonglong2 r2 = *(const ulonglong2*)(srk + 128 + 4*lq);  // contiguous
            unsigned long long rg[4] = {r1.x, r1.y, r2.x, r2.y};
            float hbf[4] = {hb.x, hb.y, hb.z, hb.w};
            #pragma unroll
            for (int i = 0; i < 4; i++) {
                unsigned long long ph = pk2(hbf[i], hbf[i]);
                #pragma unroll
                for (int j = 0; j < 4; j++)
                    fma2(acc2[i][j], ph, rg[j]);
            }
        }

        #pragma unroll
        for (int i = 0; i < 4; i++) {
            float2 v0 = upk2(acc2[i][0]);
            float2 v1 = upk2(acc2[i][1]);
            float2 v2 = upk2(acc2[i][2]);
            float2 v3 = upk2(acc2[i][3]);
            float* p = mypart + (size_t)(tb + i) * GG + g0;
            *(float4*)(p + 4*lq)       = make_float4(v0.x, v0.y, v1.x, v1.y);
            *(float4*)(p + 128 + 4*lq) = make_float4(v2.x, v2.y, v3.x, v3.y);
        }

        gbar(&sense);   // partials published

        // ---- pointwise ----
        const float* xg_t = xg_base + (size_t)t * BB * GG;
        float pre[4];
        #pragma unroll
        for (int q = 0; q < 4; q++) {
            float v = xg_t[q * HH] + bhv[q];
            #pragma unroll
            for (int s = 0; s < NKS; s++)
                v += ldcg(&g_part[s][pb * GG + q * HH + pj]);
            pre[q] = sigm(v);
        }
        c_reg = c_reg * pre[3] + pre[2] - pre[0];
        float hnew = sigm(c_reg) - pre[1];
        hbuf[pidx] = hnew;
        out[(size_t)t * BB * HH + pidx] = hnew;

        gbar(&sense);   // h published; g_part safe to overwrite
    }

    cbuf[pidx] = c_reg;
}

// ---------------- finalize ----------------
__global__ void finalize(float* __restrict__ out) {
    int i = blockIdx.x * 256 + threadIdx.x;
    if (i < 2 * BB * HH) {
        out[(size_t)TT * BB * HH + i] = g_h[i];
        out[(size_t)TT * BB * HH + 2 * BB * HH + i] = g_c[i];
    }
}

// ---------------- launch: 6 graph nodes ----------------
extern "C" void kernel_launch(void* const* d_in, const int* in_sizes, int n_in,
                              void* d_out, int out_size) {
    const float* x   = (const float*)d_in[0];
    const float* h0  = (const float*)d_in[1];
    const float* c0  = (const float*)d_in[2];
    const float* W0  = (const float*)d_in[3];
    const float* R0  = (const float*)d_in[4];
    const float* bi0 = (const float*)d_in[5];
    const float* bh0 = (const float*)d_in[6];
    const float* W1  = (const float*)d_in[7];
    const float* R1  = (const float*)d_in[8];
    const float* bi1 = (const float*)d_in[9];
    const float* bh1 = (const float*)d_in[10];
    float* out = (float*)d_out;

    float *p_xg = nullptr, *p_out0 = nullptr;
    cudaGetSymbolAddress((void**)&p_xg, g_xg);
    cudaGetSymbolAddress((void**)&p_out0, g_out0);

    cudaFuncSetAttribute(recurrent_persistent,
                         cudaFuncAttributeMaxDynamicSharedMemorySize, DYN_SMEM_BYTES);

    dim3 projGrid(PN / 128, PM / 128);

    init_state<<<256, 256>>>(h0, c0);

    proj_gemm<<<projGrid, 256>>>(x, W0, bi0, p_xg);
    recurrent_persistent<<<NB, NT, DYN_SMEM_BYTES>>>(0, R0, bh0, p_xg, p_out0);

    proj_gemm<<<projGrid, 256>>>(p_out0, W1, bi1, p_xg);
    recurrent_persistent<<<NB, NT, DYN_SMEM_BYTES>>>(1, R1, bh1, p_xg, out);

    finalize<<<256, 256>>>(out);
}

// round 16
// speedup vs baseline: 1.7229x; 1.0423x over previous
#include <cuda_runtime.h>
#include <math.h>

// Problem dims (fixed)
#define TT 512
#define BB 32
#define II 1024
#define HH 1024
#define GG 4096
#define KK 1024

#define PM (TT*BB)
#define PN GG
#define PK 1024

#define NB 128             // persistent blocks (<=148 SMs, all co-resident)
#define NT 256

// recurrent smem: R [k*34+gr] + per-warp h/reduce regions [1056 floats each]
#define SR_FLOATS (1024*34)
#define SHW_FLOATS 1056
#define DYN_SMEM_BYTES ((SR_FLOATS + 8*SHW_FLOATS) * 4)   // 173,056 B

typedef unsigned long long ull;

// ---------------- scratch (device globals; no allocation) ----------------
__device__ float g_xg[TT*BB*GG];
__device__ float g_out0[TT*BB*HH];
__device__ float g_h[2][2][BB*HH];      // [layer][buf][b*H+j], double-buffered
__device__ float g_c[2][BB*HH];

__device__ unsigned g_count = 0;
__device__ volatile unsigned g_sense_v = 0;

__device__ __forceinline__ float sigm(float x) { return 1.0f / (1.0f + expf(-x)); }

__device__ __forceinline__ ull pk2(float lo, float hi) {
    ull r; asm("mov.b64 %0, {%1,%2};" : "=l"(r) : "f"(lo), "f"(hi)); return r;
}
__device__ __forceinline__ void fma2(ull& d, ull a, ull b) {
    asm("fma.rn.f32x2 %0, %1, %2, %0;" : "+l"(d) : "l"(a), "l"(b));
}
__device__ __forceinline__ float2 upk2(ull v) {
    float2 r; asm("mov.b64 {%0,%1}, %2;" : "=f"(r.x), "=f"(r.y) : "l"(v)); return r;
}
__device__ __forceinline__ float ldcg(const float* p) {
    float v; asm volatile("ld.global.cg.f32 %0, [%1];" : "=f"(v) : "l"(p)); return v;
}
__device__ __forceinline__ float4 ldcg4(const float* p) {
    float4 v;
    asm volatile("ld.global.cg.v4.f32 {%0,%1,%2,%3}, [%4];"
                 : "=f"(v.x), "=f"(v.y), "=f"(v.z), "=f"(v.w) : "l"(p));
    return v;
}

// sense-reversing grid barrier (validated R6/R7)
__device__ __forceinline__ void gbar(unsigned* sense) {
    __syncthreads();
    if (threadIdx.x == 0) {
        unsigned s = 1u - *sense;
        *sense = s;
        __threadfence();
        if (atomicAdd(&g_count, 1u) == NB - 1u) {
            g_count = 0;
            __threadfence();
            g_sense_v = s;
        } else {
            while (g_sense_v != s) { }
        }
    }
    __syncthreads();
}

// ---------------- init ----------------
__global__ void init_state(const float* __restrict__ h0, const float* __restrict__ c0) {
    int i = blockIdx.x * 256 + threadIdx.x;   // 0..65535
    if (i < 2*BB*HH) {
        int l = i >> 15, r = i & (BB*HH - 1);
        g_h[l][0][r] = h0[i];
        g_c[l][r] = c0[i];
    }
}

// ---------------- projection GEMM (validated R7) + occupancy 2 ----------------
__global__ __launch_bounds__(256, 2) void proj_gemm(const float* __restrict__ A,
                                                    const float* __restrict__ W,
                                                    const float* __restrict__ bias,
                                                    float* __restrict__ C) {
    __shared__ __align__(16) float As[8][128];
    __shared__ __align__(16) float Bs[8][128];

    const int tid  = threadIdx.x;
    const int m0   = blockIdx.y * 128;
    const int n0   = blockIdx.x * 128;
    const int lRow = tid >> 1;
    const int lCol = (tid & 1) * 4;
    const int mr   = tid >> 4;
    const int nc   = tid & 15;

    const float* Aptr = A + (size_t)(m0 + lRow) * PK + lCol;
    const float* Wptr = W + (size_t)(n0 + lRow) * PK + lCol;

    ull acc2[8][4];
    #pragma unroll
    for (int i = 0; i < 8; i++)
        #pragma unroll
        for (int j = 0; j < 4; j++) acc2[i][j] = 0ull;

    float4 a = *(const float4*)(Aptr);
    float4 b = *(const float4*)(Wptr);

    for (int k0 = 0; k0 < PK; k0 += 8) {
        __syncthreads();
        As[lCol+0][lRow] = a.x; As[lCol+1][lRow] = a.y;
        As[lCol+2][lRow] = a.z; As[lCol+3][lRow] = a.w;
        Bs[lCol+0][lRow] = b.x; Bs[lCol+1][lRow] = b.y;
        Bs[lCol+2][lRow] = b.z; Bs[lCol+3][lRow] = b.w;
        __syncthreads();
        if (k0 + 8 < PK) {
            a = *(const float4*)(Aptr + k0 + 8);
            b = *(const float4*)(Wptr + k0 + 8);
        }
        #pragma unroll
        for (int k = 0; k < 8; k++) {
            float4 m1 = *(const float4*)&As[k][4*mr];
            float4 m2 = *(const float4*)&As[k][64 + 4*mr];
            ulonglong2 n1 = *(const ulonglong2*)&Bs[k][4*nc];
            ulonglong2 n2 = *(const ulonglong2*)&Bs[k][64 + 4*nc];
            ull rn[4] = {n1.x, n1.y, n2.x, n2.y};
            float rm[8] = {m1.x, m1.y, m1.z, m1.w, m2.x, m2.y, m2.z, m2.w};
            #pragma unroll
            for (int i = 0; i < 8; i++) {
                ull pm = pk2(rm[i], rm[i]);
                #pragma unroll
                for (int j = 0; j < 4; j++)
                    fma2(acc2[i][j], pm, rn[j]);
            }
        }
    }

    #pragma unroll
    for (int i = 0; i < 8; i++) {
        int mrow = m0 + ((i < 4) ? (4*mr + i) : (64 + 4*mr + i - 4));
        float* Crow = C + (size_t)mrow * PN + n0;
        float2 v0 = upk2(acc2[i][0]);
        float2 v1 = upk2(acc2[i][1]);
        float2 v2 = upk2(acc2[i][2]);
        float2 v3 = upk2(acc2[i][3]);
        int nq1 = 4*nc, nq2 = 64 + 4*nc;
        Crow[nq1+0] = v0.x + bias[n0+nq1+0];
        Crow[nq1+1] = v0.y + bias[n0+nq1+1];
        Crow[nq1+2] = v1.x + bias[n0+nq1+2];
        Crow[nq1+3] = v1.y + bias[n0+nq1+3];
        Crow[nq2+0] = v2.x + bias[n0+nq2+0];
        Crow[nq2+1] = v2.y + bias[n0+nq2+1];
        Crow[nq2+2] = v3.x + bias[n0+nq2+2];
        Crow[nq2+3] = v3.y + bias[n0+nq2+3];
    }
}

// ---------------- persistent recurrence v3: one barrier per step ----------------
// Block bid owns j in [bid*8, +8), all 4 gates (32 gate rows), all 32 b, K=1024.
// Warp w: K-slice [w*128,+128). R parked once: sr[k*34 + gr] (gr = q*8+jj).
// h: double-buffered in global; staged warp-private (pitch 33), LDG prefetched.
// Reduce over 8 warps in smem (reuse h region), pointwise fully block-local.
__global__ __launch_bounds__(NT) void recurrent_persistent(
    int layer, const float* __restrict__ R, const float* __restrict__ bh,
    const float* __restrict__ xg, float* __restrict__ out)
{
    extern __shared__ __align__(16) float dynsmem[];
    float* sr  = dynsmem;                    // [k*34 + gr], 1024 x 34
    float* shh = dynsmem + SR_FLOATS;        // 8 warps x 1056

    const int tid  = threadIdx.x;
    const int bid  = blockIdx.x;
    const int j0   = bid * 8;
    const int lane = tid & 31;
    const int w    = tid >> 5;

    float* sh_w = shh + w * SHW_FLOATS;

    // ---- park R transposed: sr[k*34 + gr] = R[q*H + j0+jj][k] ----
    for (int it = 0; it < 128; ++it) {
        int gr = it >> 2;
        int k  = ((it & 3) << 8) + tid;
        int q = gr >> 3, jj = gr & 7;
        sr[k * 34 + gr] = R[(size_t)(q * HH + j0 + jj) * KK + k];
    }
    __syncthreads();

    // compute mapping: lane covers 4 b (tb..tb+3) x 8 g (gq*8..+7)
    const int gq = lane & 3;
    const int tb = (lane >> 2) * 4;
    const float* srg = sr + gq * 8;

    // pointwise identity: thread owns (b=pb, j=j0+pjj)
    const int pb  = tid & 31;
    const int pjj = tid >> 5;
    const int pj  = j0 + pjj;
    float* cbuf = g_c[layer];
    float c_reg = cbuf[pb * HH + pj];

    float bhv[4];
    #pragma unroll
    for (int q = 0; q < 4; q++) bhv[q] = bh[q * HH + pj];
    const float* xg_base = xg + (size_t)pb * GG + pj;

    float* hb0 = g_h[layer][0];
    float* hb1 = g_h[layer][1];

    unsigned sense = g_sense_v;

    for (int t = 0; t < TT; ++t) {
        const float* hs = (t & 1) ? hb1 : hb0;   // read buffer
        float*       hd = (t & 1) ? hb0 : hb1;   // write buffer

        // prefetch xg for this step (independent of h)
        const float* xg_t = xg_base + (size_t)t * BB * GG;
        float xgv[4];
        #pragma unroll
        for (int q = 0; q < 4; q++) xgv[q] = ldcg(xg_t + q * HH);

        ull acc2[4][4];
        #pragma unroll
        for (int i = 0; i < 4; i++)
            #pragma unroll
            for (int j = 0; j < 4; j++) acc2[i][j] = 0ull;

        // prefetch h chunk 0 (warp-private k-slice [w*128, +32))
        float4 pf[8];
        #pragma unroll
        for (int i = 0; i < 8; ++i) {
            int f = i * 32 + lane;
            int b = f >> 3, fc = f & 7;
            pf[i] = ldcg4(hs + (size_t)b * KK + w * 128 + fc * 4);
        }

        #pragma unroll
        for (int s = 0; s < 4; ++s) {
            // store staged chunk (conflict-free: bank = 4*(l&7)+(l>>3)+const)
            #pragma unroll
            for (int i = 0; i < 8; ++i) {
                int f = i * 32 + lane;
                int b = f >> 3, fc = f & 7;
                float* d = sh_w + (fc * 4) * 33 + b;
                d[0]  = pf[i].x; d[33] = pf[i].y;
                d[66] = pf[i].z; d[99] = pf[i].w;
            }
            __syncwarp();
            // prefetch next chunk during compute
            if (s < 3) {
                #pragma unroll
                for (int i = 0; i < 8; ++i) {
                    int f = i * 32 + lane;
                    int b = f >> 3, fc = f & 7;
                    pf[i] = ldcg4(hs + (size_t)b * KK + w * 128 + (s + 1) * 32 + fc * 4);
                }
            }
            // compute 32 k
            const int kb = w * 128 + s * 32;
            #pragma unroll 4
            for (int kk = 0; kk < 32; ++kk) {
                const float* hp = sh_w + kk * 33 + tb;
                const float* rp = srg + (size_t)(kb + kk) * 34;
                ull rg0 = *(const ull*)(rp + 0);
                ull rg1 = *(const ull*)(rp + 2);
                ull rg2 = *(const ull*)(rp + 4);
                ull rg3 = *(const ull*)(rp + 6);
                float h0v = hp[0], h1v = hp[1], h2v = hp[2], h3v = hp[3];
                ull p0 = pk2(h0v, h0v), p1 = pk2(h1v, h1v);
                ull p2 = pk2(h2v, h2v), p3 = pk2(h3v, h3v);
                fma2(acc2[0][0], p0, rg0); fma2(acc2[0][1], p0, rg1);
                fma2(acc2[0][2], p0, rg2); fma2(acc2[0][3], p0, rg3);
                fma2(acc2[1][0], p1, rg0); fma2(acc2[1][1], p1, rg1);
                fma2(acc2[1][2], p1, rg2); fma2(acc2[1][3], p1, rg3);
                fma2(acc2[2][0], p2, rg0); fma2(acc2[2][1], p2, rg1);
                fma2(acc2[2][2], p2, rg2); fma2(acc2[2][3], p2, rg3);
                fma2(acc2[3][0], p3, rg0); fma2(acc2[3][1], p3, rg1);
                fma2(acc2[3][2], p3, rg2); fma2(acc2[3][3], p3, rg3);
            }
            __syncwarp();
        }

        // ---- write warp partials into sh_w (rotated i -> conflict-free) ----
        #pragma unroll
        for (int i0 = 0; i0 < 4; ++i0) {
            int i = (i0 + gq) & 3;
            int b = tb + i;
            #pragma unroll
            for (int j = 0; j < 4; ++j) {
                float2 v = upk2(acc2[i][j]);
                int gr = gq * 8 + 2 * j;
                sh_w[gr * 33 + b]       = v.x;
                sh_w[(gr + 1) * 33 + b] = v.y;
            }
        }
        __syncthreads();

        // ---- reduce over 8 warps + pointwise (block-local) ----
        float pre[4];
        #pragma unroll
        for (int q = 0; q < 4; ++q) {
            int base = (q * 8 + pjj) * 33 + pb;
            float ssum = 0.0f;
            #pragma unroll
            for (int w2 = 0; w2 < 8; ++w2) ssum += shh[w2 * SHW_FLOATS + base];
            pre[q] = sigm(xgv[q] + bhv[q] + ssum);
        }
        c_reg = c_reg * pre[3] + pre[2] - pre[0];
        float hnew = sigm(c_reg) - pre[1];
        hd[pb * HH + pj] = hnew;
        out[(size_t)t * BB * HH + pb * HH + pj] = hnew;

        gbar(&sense);   // h[t+1] published; sh_w free (block-local next step)
    }

    cbuf[pb * HH + pj] = c_reg;
}

// ---------------- finalize: (hT, cT) stacked after main output ----------------
__global__ void finalize(float* __restrict__ out) {
    int i = blockIdx.x * 256 + threadIdx.x;   // 0..65535
    if (i < 2 * BB * HH) {
        int l = i >> 15, r = i & (BB*HH - 1);
        out[(size_t)TT * BB * HH + i] = g_h[l][0][r];          // t=512 even -> buf 0
        out[(size_t)TT * BB * HH + 2 * BB * HH + i] = g_c[l][r];
    }
}

// ---------------- launch: 6 graph nodes ----------------
extern "C" void kernel_launch(void* const* d_in, const int* in_sizes, int n_in,
                              void* d_out, int out_size) {
    const float* x   = (const float*)d_in[0];
    const float* h0  = (const float*)d_in[1];
    const float* c0  = (const float*)d_in[2];
    const float* W0  = (const float*)d_in[3];
    const float* R0  = (const float*)d_in[4];
    const float* bi0 = (const float*)d_in[5];
    const float* bh0 = (const float*)d_in[6];
    const float* W1  = (const float*)d_in[7];
    const float* R1  = (const float*)d_in[8];
    const float* bi1 = (const float*)d_in[9];
    const float* bh1 = (const float*)d_in[10];
    float* out = (float*)d_out;

    float *p_xg = nullptr, *p_out0 = nullptr;
    cudaGetSymbolAddress((void**)&p_xg, g_xg);
    cudaGetSymbolAddress((void**)&p_out0, g_out0);

    cudaFuncSetAttribute(recurrent_persistent,
                         cudaFuncAttributeMaxDynamicSharedMemorySize, DYN_SMEM_BYTES);

    dim3 projGrid(PN / 128, PM / 128);

    init_state<<<256, 256>>>(h0, c0);

    proj_gemm<<<projGrid, 256>>>(x, W0, bi0, p_xg);
    recurrent_persistent<<<NB, NT, DYN_SMEM_BYTES>>>(0, R0, bh0, p_xg, p_out0);

    proj_gemm<<<projGrid, 256>>>(p_out0, W1, bi1, p_xg);
    recurrent_persistent<<<NB, NT, DYN_SMEM_BYTES>>>(1, R1, bh1, p_xg, out);

    finalize<<<256, 256>>>(out);
}